// round 3
// baseline (speedup 1.0000x reference)
#include <cuda_runtime.h>

// Problem constants
#define N_PTS   32768
#define K_CODES 8192
#define D_DIM   256
#define DECAYF  0.99f
#define OMDF    0.01f
#define EPSF    1e-5f

typedef unsigned long long ull;

// ---------------- scratch (no allocations allowed) ----------------
__device__ int   g_idx[N_PTS];
__device__ int   g_counts[K_CODES];
__device__ float g_esum[K_CODES * D_DIM];   // 8 MB
__device__ float g_c2[K_CODES];
__device__ float g_n;

// ---------------- packed f32x2 helpers (sm_103a) ----------------
__device__ __forceinline__ ull pack2(float x, float y) {
    ull r; asm("mov.b64 %0, {%1, %2};" : "=l"(r) : "f"(x), "f"(y)); return r;
}
__device__ __forceinline__ void fma2(ull& d, ull a, ull b) {
    asm("fma.rn.f32x2 %0, %1, %2, %0;" : "+l"(d) : "l"(a), "l"(b));
}
__device__ __forceinline__ float lo32(ull v) { return __uint_as_float((unsigned)v); }
__device__ __forceinline__ float hi32(ull v) { return __uint_as_float((unsigned)(v >> 32)); }

// ---------------- K0: zero scratch ----------------
__global__ void k_init() {
    int i = blockIdx.x * blockDim.x + threadIdx.x;
    if (i < K_CODES * D_DIM) g_esum[i] = 0.0f;
    if (i < K_CODES)         g_counts[i] = 0;
    if (i == 0)              g_n = 0.0f;
}

// ---------------- K1: codebook row norms ----------------
__global__ void k_c2(const float* __restrict__ cb) {
    int warp = (blockIdx.x * blockDim.x + threadIdx.x) >> 5;
    int lane = threadIdx.x & 31;
    if (warp >= K_CODES) return;
    const float* row = cb + (size_t)warp * D_DIM;
    float s = 0.0f;
    #pragma unroll
    for (int j = 0; j < D_DIM; j += 32) { float v = row[j + lane]; s += v * v; }
    #pragma unroll
    for (int o = 16; o; o >>= 1) s += __shfl_xor_sync(0xffffffffu, s, o);
    if (lane == 0) g_c2[warp] = s;
}

// ---------------- K2: fused distance + argmin ----------------
// 128 rows/block, 256 threads (16x16), 8x8 per thread, packed f32x2 FMAs.
// Double-buffered smem (1 barrier per 8-dim chunk) + register prefetch of the
// next chunk's global loads (hides L2 latency under the FMA burst).
__global__ __launch_bounds__(256, 2)
void k_nn(const float* __restrict__ z, const float* __restrict__ cb,
          float* __restrict__ out_idxf) {
    __shared__ __align__(16) float As[2][8][128];   // [buf][kk][row]
    __shared__ __align__(16) float Bs[2][8][128];   // [buf][kk][col]
    __shared__ float c2s[128];

    int tid = threadIdx.x;
    int tx = tid & 15, ty = tid >> 4;
    int rowBase = blockIdx.x * 128;

    float bval[8]; int bidx[8];
    #pragma unroll
    for (int i = 0; i < 8; i++) { bval[i] = 3.4e38f; bidx[i] = 0; }

    int lrow = tid >> 1;           // 0..127
    int lcol = (tid & 1) * 4;      // 0 or 4

    const float* zrow = z + (size_t)(rowBase + lrow) * D_DIM + lcol;

    for (int kt = 0; kt < K_CODES; kt += 128) {
        __syncthreads();  // previous tile's epilogue (c2s reads) complete
        if (tid < 128) c2s[tid] = g_c2[kt + tid];
        const float* brow = cb + (size_t)(kt + lrow) * D_DIM + lcol;

        ull acc[8][4];
        #pragma unroll
        for (int i = 0; i < 8; i++)
            #pragma unroll
            for (int j = 0; j < 4; j++) acc[i][j] = 0ULL;

        // prologue: load chunk 0 and store into buffer 0
        {
            float4 av = *(const float4*)(zrow);
            float4 bv = *(const float4*)(brow);
            As[0][lcol + 0][lrow] = av.x; As[0][lcol + 1][lrow] = av.y;
            As[0][lcol + 2][lrow] = av.z; As[0][lcol + 3][lrow] = av.w;
            Bs[0][lcol + 0][lrow] = bv.x; Bs[0][lcol + 1][lrow] = bv.y;
            Bs[0][lcol + 2][lrow] = bv.z; Bs[0][lcol + 3][lrow] = bv.w;
        }
        __syncthreads();

        int cur = 0;
        for (int d0 = 0; d0 < D_DIM; d0 += 8) {
            // prefetch next chunk into registers (clamped on last iter, no OOB)
            int d0p = (d0 + 8 < D_DIM) ? (d0 + 8) : 0;
            float4 av = *(const float4*)(zrow + d0p);
            float4 bv = *(const float4*)(brow + d0p);

            #pragma unroll
            for (int kk = 0; kk < 8; kk++) {
                float4 a0 = *(const float4*)&As[cur][kk][ty * 4];
                float4 a1 = *(const float4*)&As[cur][kk][64 + ty * 4];
                ulonglong2 b01 = *(const ulonglong2*)&Bs[cur][kk][tx * 4];
                ulonglong2 b23 = *(const ulonglong2*)&Bs[cur][kk][64 + tx * 4];
                float ar[8] = {a0.x, a0.y, a0.z, a0.w, a1.x, a1.y, a1.z, a1.w};
                #pragma unroll
                for (int i = 0; i < 8; i++) {
                    ull ap = pack2(ar[i], ar[i]);
                    fma2(acc[i][0], ap, b01.x);
                    fma2(acc[i][1], ap, b01.y);
                    fma2(acc[i][2], ap, b23.x);
                    fma2(acc[i][3], ap, b23.y);
                }
            }

            // store prefetched chunk into the other buffer
            int nxt = cur ^ 1;
            As[nxt][lcol + 0][lrow] = av.x; As[nxt][lcol + 1][lrow] = av.y;
            As[nxt][lcol + 2][lrow] = av.z; As[nxt][lcol + 3][lrow] = av.w;
            Bs[nxt][lcol + 0][lrow] = bv.x; Bs[nxt][lcol + 1][lrow] = bv.y;
            Bs[nxt][lcol + 2][lrow] = bv.z; Bs[nxt][lcol + 3][lrow] = bv.w;
            cur = nxt;
            __syncthreads();
        }

        // epilogue: per-row argmin over this 128-col tile
        #pragma unroll
        for (int i = 0; i < 8; i++) {
            float mv = 3.4e38f; int mi = 0x7fffffff;
            #pragma unroll
            for (int j = 0; j < 4; j++) {
                int cl = (j < 2) ? (tx * 4 + 2 * j) : (64 + tx * 4 + 2 * (j - 2));
                float s0 = lo32(acc[i][j]), s1 = hi32(acc[i][j]);
                float dv0 = c2s[cl]     - 2.0f * s0;
                float dv1 = c2s[cl + 1] - 2.0f * s1;
                int c0 = kt + cl, c1 = c0 + 1;
                if (dv0 < mv || (dv0 == mv && c0 < mi)) { mv = dv0; mi = c0; }
                if (dv1 < mv || (dv1 == mv && c1 < mi)) { mv = dv1; mi = c1; }
            }
            #pragma unroll
            for (int o = 8; o; o >>= 1) {
                float ov = __shfl_xor_sync(0xffffffffu, mv, o);
                int   oi = __shfl_xor_sync(0xffffffffu, mi, o);
                if (ov < mv || (ov == mv && oi < mi)) { mv = ov; mi = oi; }
            }
            if (mv < bval[i] || (mv == bval[i] && mi < bidx[i])) { bval[i] = mv; bidx[i] = mi; }
        }
    }

    if (tx == 0) {
        #pragma unroll
        for (int i = 0; i < 8; i++) {
            int r = rowBase + ((i < 4) ? (ty * 4 + i) : (64 + ty * 4 + (i - 4)));
            g_idx[r] = bidx[i];
            out_idxf[r] = (float)bidx[i];
        }
    }
}

// ---------------- K3: gather quantized + scatter segment sums ----------------
__global__ void k_scatter(const float* __restrict__ z, const float* __restrict__ cb,
                          float* __restrict__ out_quant) {
    int warp = (blockIdx.x * blockDim.x + threadIdx.x) >> 5;
    int lane = threadIdx.x & 31;
    if (warp >= N_PTS) return;
    int idx = g_idx[warp];
    const float* zr = z + (size_t)warp * D_DIM;
    const float* cr = cb + (size_t)idx * D_DIM;
    float* qr = out_quant + (size_t)warp * D_DIM;
    float* er = g_esum + (size_t)idx * D_DIM;
    #pragma unroll
    for (int j = 0; j < D_DIM; j += 32) {
        qr[j + lane] = cr[j + lane];
        atomicAdd(&er[j + lane], zr[j + lane]);
    }
    if (lane == 0) atomicAdd(&g_counts[idx], 1);
}

// ---------------- K4: new cluster size + n reduction ----------------
__global__ void k_cs(const float* __restrict__ cs, float* __restrict__ out_cs) {
    int k = blockIdx.x * blockDim.x + threadIdx.x;
    float v = 0.0f;
    if (k < K_CODES) {
        v = DECAYF * cs[k] + OMDF * (float)g_counts[k];
        out_cs[k] = v;
    }
    __shared__ float red[256];
    red[threadIdx.x] = v;
    __syncthreads();
    #pragma unroll
    for (int s = 128; s; s >>= 1) {
        if (threadIdx.x < s) red[threadIdx.x] += red[threadIdx.x + s];
        __syncthreads();
    }
    if (threadIdx.x == 0) atomicAdd(&g_n, red[0]);
}

// ---------------- K5: EMA avg + smoothed codebook ----------------
__global__ void k_final(const float* __restrict__ avg, const float* __restrict__ out_cs_r,
                        float* __restrict__ out_cb, float* __restrict__ out_avg) {
    int i = blockIdx.x * blockDim.x + threadIdx.x;
    if (i >= K_CODES * D_DIM) return;
    int k = i >> 8;  // D = 256
    float n = g_n;
    float ncs = out_cs_r[k];
    float smoothed = (ncs + EPSF) / (n + (float)K_CODES * EPSF) * n;
    float a = DECAYF * avg[i] + OMDF * g_esum[i];
    out_avg[i] = a;
    out_cb[i] = a / smoothed;
}

// ---------------- launch ----------------
extern "C" void kernel_launch(void* const* d_in, const int* in_sizes, int n_in,
                              void* d_out, int out_size) {
    const float* z   = (const float*)d_in[0];
    const float* cb  = (const float*)d_in[1];
    const float* avg = (const float*)d_in[2];
    const float* cs  = (const float*)d_in[3];

    float* out       = (float*)d_out;
    float* out_quant = out;                                  // N*D
    float* out_idx   = out_quant + (size_t)N_PTS * D_DIM;    // N
    float* out_cb    = out_idx + N_PTS;                      // K*D
    float* out_avg   = out_cb + (size_t)K_CODES * D_DIM;     // K*D
    float* out_cs    = out_avg + (size_t)K_CODES * D_DIM;    // K

    k_init   <<<(K_CODES * D_DIM + 255) / 256, 256>>>();
    k_c2     <<<(K_CODES * 32 + 255) / 256, 256>>>(cb);
    k_nn     <<<N_PTS / 128, 256>>>(z, cb, out_idx);
    k_scatter<<<(N_PTS * 32 + 255) / 256, 256>>>(z, cb, out_quant);
    k_cs     <<<(K_CODES + 255) / 256, 256>>>(cs, out_cs);
    k_final  <<<(K_CODES * D_DIM + 255) / 256, 256>>>(avg, out_cs, out_cb, out_avg);
}

// round 5
// speedup vs baseline: 1.0772x; 1.0772x over previous
#include <cuda_runtime.h>

// Problem constants
#define N_PTS   32768
#define K_CODES 8192
#define D_DIM   256
#define DECAYF  0.99f
#define OMDF    0.01f
#define EPSF    1e-5f

typedef unsigned long long ull;

// ---------------- scratch (no allocations allowed) ----------------
__device__ int   g_idx[N_PTS];
__device__ int   g_counts[K_CODES];
__device__ float g_esum[K_CODES * D_DIM];   // 8 MB
__device__ float g_c2[K_CODES];
__device__ float g_n;

// ---------------- packed f32x2 helpers (sm_103a) ----------------
__device__ __forceinline__ ull pack2(float x, float y) {
    ull r; asm("mov.b64 %0, {%1, %2};" : "=l"(r) : "f"(x), "f"(y)); return r;
}
__device__ __forceinline__ void fma2(ull& d, ull a, ull b) {
    asm("fma.rn.f32x2 %0, %1, %2, %0;" : "+l"(d) : "l"(a), "l"(b));
}
__device__ __forceinline__ float lo32(ull v) { return __uint_as_float((unsigned)v); }
__device__ __forceinline__ float hi32(ull v) { return __uint_as_float((unsigned)(v >> 32)); }

// ---------------- K0: zero scratch ----------------
__global__ void k_init() {
    int i = blockIdx.x * blockDim.x + threadIdx.x;
    if (i < K_CODES * D_DIM) g_esum[i] = 0.0f;
    if (i < K_CODES)         g_counts[i] = 0;
    if (i == 0)              g_n = 0.0f;
}

// ---------------- K1: codebook row norms ----------------
__global__ void k_c2(const float* __restrict__ cb) {
    int warp = (blockIdx.x * blockDim.x + threadIdx.x) >> 5;
    int lane = threadIdx.x & 31;
    if (warp >= K_CODES) return;
    const float* row = cb + (size_t)warp * D_DIM;
    float s = 0.0f;
    #pragma unroll
    for (int j = 0; j < D_DIM; j += 32) { float v = row[j + lane]; s += v * v; }
    #pragma unroll
    for (int o = 16; o; o >>= 1) s += __shfl_xor_sync(0xffffffffu, s, o);
    if (lane == 0) g_c2[warp] = s;
}

// ---------------- K2: fused distance + argmin ----------------
// 128 threads/block, tile 128 rows x 128 cols per k-step, 16x8 outputs/thread.
// Accumulators packed as M-row PAIRS (f32x2): A loads give natural pairs from
// shared (no MOV duplication); only the 8 B values per kk need pack2.
// Double-buffered smem (1 barrier/chunk) + register prefetch of next chunk.
__global__ __launch_bounds__(128, 2)
void k_nn(const float* __restrict__ z, const float* __restrict__ cb,
          float* __restrict__ out_idxf) {
    __shared__ __align__(16) float As[2][8][128];   // [buf][kk][row]
    __shared__ __align__(16) float Bs[2][8][128];   // [buf][kk][col]
    __shared__ float c2s[128];

    int tid = threadIdx.x;            // 0..127
    int tx = tid & 15;                // col group
    int ty = tid >> 4;                // 0..7, owns rows ty*16 .. ty*16+15
    int rowBase = blockIdx.x * 128;

    // per-thread best (16 rows = 8 pairs; track per scalar row)
    float bval[16]; int bidx[16];
    #pragma unroll
    for (int i = 0; i < 16; i++) { bval[i] = 3.4e38f; bidx[i] = 0; }

    const float* zrow = z + (size_t)(rowBase + tid) * D_DIM;

    for (int kt = 0; kt < K_CODES; kt += 128) {
        __syncthreads();  // prev tile epilogue (c2s reads) complete
        c2s[tid] = g_c2[kt + tid];
        const float* brow = cb + (size_t)(kt + tid) * D_DIM;

        // acc[p][c]: pair p = rows (ty*16+2p, ty*16+2p+1); c = 8 cols
        ull acc[8][8];
        #pragma unroll
        for (int p = 0; p < 8; p++)
            #pragma unroll
            for (int c = 0; c < 8; c++) acc[p][c] = 0ULL;

        // prologue: chunk 0 -> buffer 0
        {
            float4 a0 = *(const float4*)(zrow);
            float4 a1 = *(const float4*)(zrow + 4);
            float4 b0 = *(const float4*)(brow);
            float4 b1 = *(const float4*)(brow + 4);
            As[0][0][tid] = a0.x; As[0][1][tid] = a0.y; As[0][2][tid] = a0.z; As[0][3][tid] = a0.w;
            As[0][4][tid] = a1.x; As[0][5][tid] = a1.y; As[0][6][tid] = a1.z; As[0][7][tid] = a1.w;
            Bs[0][0][tid] = b0.x; Bs[0][1][tid] = b0.y; Bs[0][2][tid] = b0.z; Bs[0][3][tid] = b0.w;
            Bs[0][4][tid] = b1.x; Bs[0][5][tid] = b1.y; Bs[0][6][tid] = b1.z; Bs[0][7][tid] = b1.w;
        }
        __syncthreads();

        int cur = 0;
        for (int d0 = 0; d0 < D_DIM; d0 += 8) {
            // prefetch next chunk (clamped on last iter; same-thread WAW safe)
            int d0p = (d0 + 8 < D_DIM) ? (d0 + 8) : 0;
            float4 pa0 = *(const float4*)(zrow + d0p);
            float4 pa1 = *(const float4*)(zrow + d0p + 4);
            float4 pb0 = *(const float4*)(brow + d0p);
            float4 pb1 = *(const float4*)(brow + d0p + 4);

            #pragma unroll
            for (int kk = 0; kk < 8; kk++) {
                // A: 16 rows = 8 natural f32x2 pairs (4x LDS.128, broadcast across tx)
                ulonglong2 ap01 = *(const ulonglong2*)&As[cur][kk][ty * 16];
                ulonglong2 ap23 = *(const ulonglong2*)&As[cur][kk][ty * 16 + 4];
                ulonglong2 ap45 = *(const ulonglong2*)&As[cur][kk][ty * 16 + 8];
                ulonglong2 ap67 = *(const ulonglong2*)&As[cur][kk][ty * 16 + 12];
                ull ap[8] = {ap01.x, ap01.y, ap23.x, ap23.y, ap45.x, ap45.y, ap67.x, ap67.y};
                // B: 8 cols (2x LDS.128), duplicate each into a pair
                float4 bb0 = *(const float4*)&Bs[cur][kk][tx * 4];
                float4 bb1 = *(const float4*)&Bs[cur][kk][64 + tx * 4];
                float bs[8] = {bb0.x, bb0.y, bb0.z, bb0.w, bb1.x, bb1.y, bb1.z, bb1.w};
                ull bd[8];
                #pragma unroll
                for (int c = 0; c < 8; c++) bd[c] = pack2(bs[c], bs[c]);
                #pragma unroll
                for (int p = 0; p < 8; p++)
                    #pragma unroll
                    for (int c = 0; c < 8; c++)
                        fma2(acc[p][c], ap[p], bd[c]);
            }

            // store prefetched chunk into the other buffer
            int nxt = cur ^ 1;
            As[nxt][0][tid] = pa0.x; As[nxt][1][tid] = pa0.y; As[nxt][2][tid] = pa0.z; As[nxt][3][tid] = pa0.w;
            As[nxt][4][tid] = pa1.x; As[nxt][5][tid] = pa1.y; As[nxt][6][tid] = pa1.z; As[nxt][7][tid] = pa1.w;
            Bs[nxt][0][tid] = pb0.x; Bs[nxt][1][tid] = pb0.y; Bs[nxt][2][tid] = pb0.z; Bs[nxt][3][tid] = pb0.w;
            Bs[nxt][4][tid] = pb1.x; Bs[nxt][5][tid] = pb1.y; Bs[nxt][6][tid] = pb1.z; Bs[nxt][7][tid] = pb1.w;
            cur = nxt;
            __syncthreads();
        }

        // epilogue: per-row argmin over this 128-col tile
        #pragma unroll
        for (int p = 0; p < 8; p++) {
            float mv0 = 3.4e38f, mv1 = 3.4e38f;
            int   mi0 = 0x7fffffff, mi1 = 0x7fffffff;
            #pragma unroll
            for (int c = 0; c < 8; c++) {
                int cl = (c < 4) ? (tx * 4 + c) : (64 + tx * 4 + (c - 4));
                float c2v = c2s[cl];
                float dv0 = c2v - 2.0f * lo32(acc[p][c]);   // row 2p
                float dv1 = c2v - 2.0f * hi32(acc[p][c]);   // row 2p+1
                int ci = kt + cl;
                if (dv0 < mv0 || (dv0 == mv0 && ci < mi0)) { mv0 = dv0; mi0 = ci; }
                if (dv1 < mv1 || (dv1 == mv1 && ci < mi1)) { mv1 = dv1; mi1 = ci; }
            }
            // reduce across tx (offsets 8,4,2,1 stay within the 16-lane tx group)
            #pragma unroll
            for (int o = 8; o; o >>= 1) {
                float ov0 = __shfl_xor_sync(0xffffffffu, mv0, o);
                int   oi0 = __shfl_xor_sync(0xffffffffu, mi0, o);
                float ov1 = __shfl_xor_sync(0xffffffffu, mv1, o);
                int   oi1 = __shfl_xor_sync(0xffffffffu, mi1, o);
                if (ov0 < mv0 || (ov0 == mv0 && oi0 < mi0)) { mv0 = ov0; mi0 = oi0; }
                if (ov1 < mv1 || (ov1 == mv1 && oi1 < mi1)) { mv1 = ov1; mi1 = oi1; }
            }
            if (mv0 < bval[2*p]   || (mv0 == bval[2*p]   && mi0 < bidx[2*p]))   { bval[2*p]   = mv0; bidx[2*p]   = mi0; }
            if (mv1 < bval[2*p+1] || (mv1 == bval[2*p+1] && mi1 < bidx[2*p+1])) { bval[2*p+1] = mv1; bidx[2*p+1] = mi1; }
        }
    }

    if (tx == 0) {
        #pragma unroll
        for (int i = 0; i < 16; i++) {
            int r = rowBase + ty * 16 + i;
            g_idx[r] = bidx[i];
            out_idxf[r] = (float)bidx[i];
        }
    }
}

// ---------------- K3: gather quantized + scatter segment sums ----------------
__global__ void k_scatter(const float* __restrict__ z, const float* __restrict__ cb,
                          float* __restrict__ out_quant) {
    int warp = (blockIdx.x * blockDim.x + threadIdx.x) >> 5;
    int lane = threadIdx.x & 31;
    if (warp >= N_PTS) return;
    int idx = g_idx[warp];
    const float* zr = z + (size_t)warp * D_DIM;
    const float* cr = cb + (size_t)idx * D_DIM;
    float* qr = out_quant + (size_t)warp * D_DIM;
    float* er = g_esum + (size_t)idx * D_DIM;
    #pragma unroll
    for (int j = 0; j < D_DIM; j += 32) {
        qr[j + lane] = cr[j + lane];
        atomicAdd(&er[j + lane], zr[j + lane]);
    }
    if (lane == 0) atomicAdd(&g_counts[idx], 1);
}

// ---------------- K4: new cluster size + n reduction ----------------
__global__ void k_cs(const float* __restrict__ cs, float* __restrict__ out_cs) {
    int k = blockIdx.x * blockDim.x + threadIdx.x;
    float v = 0.0f;
    if (k < K_CODES) {
        v = DECAYF * cs[k] + OMDF * (float)g_counts[k];
        out_cs[k] = v;
    }
    __shared__ float red[256];
    red[threadIdx.x] = v;
    __syncthreads();
    #pragma unroll
    for (int s = 128; s; s >>= 1) {
        if (threadIdx.x < s) red[threadIdx.x] += red[threadIdx.x + s];
        __syncthreads();
    }
    if (threadIdx.x == 0) atomicAdd(&g_n, red[0]);
}

// ---------------- K5: EMA avg + smoothed codebook ----------------
__global__ void k_final(const float* __restrict__ avg, const float* __restrict__ out_cs_r,
                        float* __restrict__ out_cb, float* __restrict__ out_avg) {
    int i = blockIdx.x * blockDim.x + threadIdx.x;
    if (i >= K_CODES * D_DIM) return;
    int k = i >> 8;  // D = 256
    float n = g_n;
    float ncs = out_cs_r[k];
    float smoothed = (ncs + EPSF) / (n + (float)K_CODES * EPSF) * n;
    float a = DECAYF * avg[i] + OMDF * g_esum[i];
    out_avg[i] = a;
    out_cb[i] = a / smoothed;
}

// ---------------- launch ----------------
extern "C" void kernel_launch(void* const* d_in, const int* in_sizes, int n_in,
                              void* d_out, int out_size) {
    const float* z   = (const float*)d_in[0];
    const float* cb  = (const float*)d_in[1];
    const float* avg = (const float*)d_in[2];
    const float* cs  = (const float*)d_in[3];

    float* out       = (float*)d_out;
    float* out_quant = out;                                  // N*D
    float* out_idx   = out_quant + (size_t)N_PTS * D_DIM;    // N
    float* out_cb    = out_idx + N_PTS;                      // K*D
    float* out_avg   = out_cb + (size_t)K_CODES * D_DIM;     // K*D
    float* out_cs    = out_avg + (size_t)K_CODES * D_DIM;    // K

    k_init   <<<(K_CODES * D_DIM + 255) / 256, 256>>>();
    k_c2     <<<(K_CODES * 32 + 255) / 256, 256>>>(cb);
    k_nn     <<<N_PTS / 128, 128>>>(z, cb, out_idx);
    k_scatter<<<(N_PTS * 32 + 255) / 256, 256>>>(z, cb, out_quant);
    k_cs     <<<(K_CODES + 255) / 256, 256>>>(cs, out_cs);
    k_final  <<<(K_CODES * D_DIM + 255) / 256, 256>>>(avg, out_cs, out_cb, out_avg);
}

// round 11
// speedup vs baseline: 1.2206x; 1.1330x over previous
#include <cuda_runtime.h>
#include <cstdint>

#define N_PTS   32768
#define K_CODES 8192
#define D_DIM   256
#define DECAYF  0.99f
#define OMDF    0.01f
#define EPSF    1e-5f

// ---------------- scratch (no allocations allowed) ----------------
__device__ int   g_idx[N_PTS];
__device__ int   g_counts[K_CODES];
__device__ float g_esum[K_CODES * D_DIM];   // 8 MB
__device__ float g_c2[K_CODES];
__device__ float g_n;

// ---------------- smem layout (floats) ----------------
#define OFF_A    0                      /* 128 x 260 fp32 z tile      */
#define OFF_BH0  33280                  /* 128 x 36 tf32 hi, buf 0    */
#define OFF_BL0  37888
#define OFF_BH1  42496
#define OFF_BL1  47104
#define OFF_C2   51712                  /* 128 c2 values              */
#define OFF_RED  51840                  /* 4x128 val + 4x128 idx      */
#define SMEM_FLOATS 52864
#define SMEM_BYTES  (SMEM_FLOATS * 4)   /* 211,456 B */

// ---------------- tf32 helpers (baseline PTX, sm_80+) ----------------
__device__ __forceinline__ uint32_t f2tf32(float v) {
    uint32_t r; asm("cvt.rna.tf32.f32 %0, %1;" : "=r"(r) : "f"(v)); return r;
}
__device__ __forceinline__ void mma_tf32(float* c, const uint32_t* a, const uint32_t* b) {
    asm volatile("mma.sync.aligned.m16n8k8.row.col.f32.tf32.tf32.f32 "
        "{%0,%1,%2,%3}, {%4,%5,%6,%7}, {%8,%9}, {%0,%1,%2,%3};"
        : "+f"(c[0]), "+f"(c[1]), "+f"(c[2]), "+f"(c[3])
        : "r"(a[0]), "r"(a[1]), "r"(a[2]), "r"(a[3]), "r"(b[0]), "r"(b[1]));
}

// ---------------- K0: zero scratch ----------------
__global__ void k_init() {
    int i = blockIdx.x * blockDim.x + threadIdx.x;
    if (i < K_CODES * D_DIM) g_esum[i] = 0.0f;
    if (i < K_CODES)         g_counts[i] = 0;
    if (i == 0)              g_n = 0.0f;
}

// ---------------- K1: codebook row norms ----------------
__global__ void k_c2(const float* __restrict__ cb) {
    int warp = (blockIdx.x * blockDim.x + threadIdx.x) >> 5;
    int lane = threadIdx.x & 31;
    if (warp >= K_CODES) return;
    const float* row = cb + (size_t)warp * D_DIM;
    float s = 0.0f;
    #pragma unroll
    for (int j = 0; j < D_DIM; j += 32) { float v = row[j + lane]; s += v * v; }
    #pragma unroll
    for (int o = 16; o; o >>= 1) s += __shfl_xor_sync(0xffffffffu, s, o);
    if (lane == 0) g_c2[warp] = s;
}

// ---------------- K2: tf32 mma.sync distance + argmin ----------------
// 256 thr (8 warps, 2x4 m x n). CTA tile 128 rows x 128 cols per n-tile.
// A (z) resident fp32 in smem, split to tf32(hi,lo) on the fly.
// B (codebook) streamed k32 chunks, split during copy (BH/BL), double-buffered.
// 3 MMAs per fragment: zh*ch + zh*cl + zl*ch (zl*cl dropped, ~2^-22).
__global__ __launch_bounds__(256, 1)
void k_nn_mma(const float* __restrict__ z, const float* __restrict__ cb,
              float* __restrict__ out_idxf) {
    extern __shared__ float smem[];
    float* As  = smem + OFF_A;
    float* c2s = smem + OFF_C2;
    float* BH[2] = { smem + OFF_BH0, smem + OFF_BH1 };
    float* BL[2] = { smem + OFF_BL0, smem + OFF_BL1 };

    int tid = threadIdx.x;
    int wid = tid >> 5, lane = tid & 31;
    int wm = wid >> 2, wn = wid & 3;         // warp 2x4 grid
    int qr = lane >> 2, ql = lane & 3;       // groupID, thread-in-group
    int rowBase = blockIdx.x * 128;
    int arowbase = wm * 64 + qr;             // + mf*16 (+8)
    int nbase = wn * 32 + qr;                // + nf*8

    // ---- A fill: 128 rows x 256 k, fp32, pad 260 ----
    {
        int row = tid >> 1, half = tid & 1;
        const float4* zr = (const float4*)(z + (size_t)(rowBase + row) * D_DIM + half * 128);
        float4* dst = (float4*)(As + (size_t)row * 260 + half * 128);
        #pragma unroll
        for (int g = 0; g < 32; g++) dst[g] = zr[g];
    }
    __syncthreads();

    float bval[8]; int bidx[8];
    #pragma unroll
    for (int i = 0; i < 8; i++) { bval[i] = 3.4e38f; bidx[i] = 0x7fffffff; }

    int fr0 = wid * 16;   // this warp's B-fill rows

    #pragma unroll 1
    for (int nt = 0; nt < K_CODES / 128; nt++) {
        int ntBase = nt * 128;
        if (tid < 128) c2s[tid] = g_c2[ntBase + tid];

        float acc[4][4][4];
        #pragma unroll
        for (int mf = 0; mf < 4; mf++)
            #pragma unroll
            for (int nf = 0; nf < 4; nf++)
                #pragma unroll
                for (int e = 0; e < 4; e++) acc[mf][nf][e] = 0.0f;

        // chunk 0 fill
        {
            float v[16];
            #pragma unroll
            for (int rr = 0; rr < 16; rr++)
                v[rr] = cb[(size_t)(ntBase + fr0 + rr) * D_DIM + lane];
            #pragma unroll
            for (int rr = 0; rr < 16; rr++) {
                float hf = __uint_as_float(f2tf32(v[rr]));
                float lf = __uint_as_float(f2tf32(v[rr] - hf));
                BH[0][(fr0 + rr) * 36 + lane] = hf;
                BL[0][(fr0 + rr) * 36 + lane] = lf;
            }
        }
        __syncthreads();

        #pragma unroll 1
        for (int c = 0; c < 8; c++) {
            int use = c & 1;
            float v[16];
            if (c < 7) {   // prefetch next chunk (L2 latency overlaps MMAs)
                int kc = (c + 1) * 32;
                #pragma unroll
                for (int rr = 0; rr < 16; rr++)
                    v[rr] = cb[(size_t)(ntBase + fr0 + rr) * D_DIM + kc + lane];
            }

            #pragma unroll
            for (int j = 0; j < 4; j++) {
                int kA = c * 32 + j * 8;
                // A fragments: load fp32, split to tf32 hi/lo
                uint32_t ah[4][4], al[4][4];
                #pragma unroll
                for (int mf = 0; mf < 4; mf++) {
                    const float* ap = As + (size_t)(arowbase + mf * 16) * 260 + kA + ql;
                    float v0 = ap[0], v1 = ap[8 * 260], v2 = ap[4], v3 = ap[8 * 260 + 4];
                    ah[mf][0] = f2tf32(v0); al[mf][0] = f2tf32(v0 - __uint_as_float(ah[mf][0]));
                    ah[mf][1] = f2tf32(v1); al[mf][1] = f2tf32(v1 - __uint_as_float(ah[mf][1]));
                    ah[mf][2] = f2tf32(v2); al[mf][2] = f2tf32(v2 - __uint_as_float(ah[mf][2]));
                    ah[mf][3] = f2tf32(v3); al[mf][3] = f2tf32(v3 - __uint_as_float(ah[mf][3]));
                }
                // B fragments (pre-split in smem)
                uint32_t bh[4][2], bl[4][2];
                #pragma unroll
                for (int nf = 0; nf < 4; nf++) {
                    int n0 = (nbase + nf * 8) * 36 + j * 8 + ql;
                    bh[nf][0] = __float_as_uint(BH[use][n0]);
                    bh[nf][1] = __float_as_uint(BH[use][n0 + 4]);
                    bl[nf][0] = __float_as_uint(BL[use][n0]);
                    bl[nf][1] = __float_as_uint(BL[use][n0 + 4]);
                }
                #pragma unroll
                for (int mf = 0; mf < 4; mf++)
                    #pragma unroll
                    for (int nf = 0; nf < 4; nf++) {
                        mma_tf32(acc[mf][nf], ah[mf], bh[nf]);
                        mma_tf32(acc[mf][nf], ah[mf], bl[nf]);
                        mma_tf32(acc[mf][nf], al[mf], bh[nf]);
                    }
            }

            if (c < 7) {   // split + store prefetched chunk into other buffer
                #pragma unroll
                for (int rr = 0; rr < 16; rr++) {
                    float hf = __uint_as_float(f2tf32(v[rr]));
                    float lf = __uint_as_float(f2tf32(v[rr] - hf));
                    BH[use ^ 1][(fr0 + rr) * 36 + lane] = hf;
                    BL[use ^ 1][(fr0 + rr) * 36 + lane] = lf;
                }
            }
            __syncthreads();
        }

        // epilogue: dist = c2 - 2*s, fold into running per-row argmin
        #pragma unroll
        for (int mf = 0; mf < 4; mf++)
            #pragma unroll
            for (int nf = 0; nf < 4; nf++) {
                int col = wn * 32 + nf * 8 + ql * 2;
                float c2a = c2s[col], c2b = c2s[col + 1];
                int ca = ntBase + col, cbx = ca + 1;
                float d00 = c2a - 2.0f * acc[mf][nf][0];   // row base,  col
                float d01 = c2b - 2.0f * acc[mf][nf][1];   // row base,  col+1
                float d10 = c2a - 2.0f * acc[mf][nf][2];   // row base+8, col
                float d11 = c2b - 2.0f * acc[mf][nf][3];
                int i0 = mf * 2, i1 = mf * 2 + 1;
                if (d00 < bval[i0] || (d00 == bval[i0] && ca  < bidx[i0])) { bval[i0] = d00; bidx[i0] = ca; }
                if (d01 < bval[i0] || (d01 == bval[i0] && cbx < bidx[i0])) { bval[i0] = d01; bidx[i0] = cbx; }
                if (d10 < bval[i1] || (d10 == bval[i1] && ca  < bidx[i1])) { bval[i1] = d10; bidx[i1] = ca; }
                if (d11 < bval[i1] || (d11 == bval[i1] && cbx < bidx[i1])) { bval[i1] = d11; bidx[i1] = cbx; }
            }
        __syncthreads();   // protect c2s for next n-tile
    }

    // ---- final reduce: across ql lanes, then across warp_n via smem ----
    #pragma unroll
    for (int i = 0; i < 8; i++) {
        #pragma unroll
        for (int o = 1; o <= 2; o <<= 1) {
            float ov = __shfl_xor_sync(0xffffffffu, bval[i], o);
            int   oi = __shfl_xor_sync(0xffffffffu, bidx[i], o);
            if (ov < bval[i] || (ov == bval[i] && oi < bidx[i])) { bval[i] = ov; bidx[i] = oi; }
        }
    }
    float* sval = smem + OFF_RED;          // [4][128]
    int*   sidx = (int*)(sval + 512);
    if (ql == 0) {
        #pragma unroll
        for (int i = 0; i < 8; i++) {
            int rl = wm * 64 + (i >> 1) * 16 + (i & 1) * 8 + qr;
            sval[wn * 128 + rl] = bval[i];
            sidx[wn * 128 + rl] = bidx[i];
        }
    }
    __syncthreads();
    if (tid < 128) {
        float v = sval[tid]; int ix = sidx[tid];
        #pragma unroll
        for (int w = 1; w < 4; w++) {
            float v2 = sval[w * 128 + tid]; int i2 = sidx[w * 128 + tid];
            if (v2 < v || (v2 == v && i2 < ix)) { v = v2; ix = i2; }
        }
        g_idx[rowBase + tid] = ix;
        out_idxf[rowBase + tid] = (float)ix;
    }
}

// ---------------- K3: gather quantized + scatter segment sums ----------------
__global__ void k_scatter(const float* __restrict__ z, const float* __restrict__ cb,
                          float* __restrict__ out_quant) {
    int warp = (blockIdx.x * blockDim.x + threadIdx.x) >> 5;
    int lane = threadIdx.x & 31;
    if (warp >= N_PTS) return;
    int idx = g_idx[warp];
    const float* zr = z + (size_t)warp * D_DIM;
    const float* cr = cb + (size_t)idx * D_DIM;
    float* qr = out_quant + (size_t)warp * D_DIM;
    float* er = g_esum + (size_t)idx * D_DIM;
    #pragma unroll
    for (int j = 0; j < D_DIM; j += 32) {
        qr[j + lane] = cr[j + lane];
        atomicAdd(&er[j + lane], zr[j + lane]);
    }
    if (lane == 0) atomicAdd(&g_counts[idx], 1);
}

// ---------------- K4: new cluster size + n reduction ----------------
__global__ void k_cs(const float* __restrict__ cs, float* __restrict__ out_cs) {
    int k = blockIdx.x * blockDim.x + threadIdx.x;
    float v = 0.0f;
    if (k < K_CODES) {
        v = DECAYF * cs[k] + OMDF * (float)g_counts[k];
        out_cs[k] = v;
    }
    __shared__ float red[256];
    red[threadIdx.x] = v;
    __syncthreads();
    #pragma unroll
    for (int s = 128; s; s >>= 1) {
        if (threadIdx.x < s) red[threadIdx.x] += red[threadIdx.x + s];
        __syncthreads();
    }
    if (threadIdx.x == 0) atomicAdd(&g_n, red[0]);
}

// ---------------- K5: EMA avg + smoothed codebook ----------------
__global__ void k_final(const float* __restrict__ avg, const float* __restrict__ out_cs_r,
                        float* __restrict__ out_cb, float* __restrict__ out_avg) {
    int i = blockIdx.x * blockDim.x + threadIdx.x;
    if (i >= K_CODES * D_DIM) return;
    int k = i >> 8;  // D = 256
    float n = g_n;
    float ncs = out_cs_r[k];
    float smoothed = (ncs + EPSF) / (n + (float)K_CODES * EPSF) * n;
    float a = DECAYF * avg[i] + OMDF * g_esum[i];
    out_avg[i] = a;
    out_cb[i] = a / smoothed;
}

// ---------------- launch ----------------
extern "C" void kernel_launch(void* const* d_in, const int* in_sizes, int n_in,
                              void* d_out, int out_size) {
    const float* z   = (const float*)d_in[0];
    const float* cb  = (const float*)d_in[1];
    const float* avg = (const float*)d_in[2];
    const float* cs  = (const float*)d_in[3];

    float* out       = (float*)d_out;
    float* out_quant = out;                                  // N*D
    float* out_idx   = out_quant + (size_t)N_PTS * D_DIM;    // N
    float* out_cb    = out_idx + N_PTS;                      // K*D
    float* out_avg   = out_cb + (size_t)K_CODES * D_DIM;     // K*D
    float* out_cs    = out_avg + (size_t)K_CODES * D_DIM;    // K

    // unconditional + idempotent (no static guards allowed by harness rules)
    cudaFuncSetAttribute(k_nn_mma, cudaFuncAttributeMaxDynamicSharedMemorySize, SMEM_BYTES);

    k_init   <<<(K_CODES * D_DIM + 255) / 256, 256>>>();
    k_c2     <<<(K_CODES * 32 + 255) / 256, 256>>>(cb);
    k_nn_mma <<<N_PTS / 128, 256, SMEM_BYTES>>>(z, cb, out_idx);
    k_scatter<<<(N_PTS * 32 + 255) / 256, 256>>>(z, cb, out_quant);
    k_cs     <<<(K_CODES + 255) / 256, 256>>>(cs, out_cs);
    k_final  <<<(K_CODES * D_DIM + 255) / 256, 256>>>(avg, out_cs, out_cb, out_avg);
}